// round 14
// baseline (speedup 1.0000x reference)
#include <cuda_runtime.h>
#include <math.h>

#define NH 76
#define NW 76
#define NA 3
#define NCLS 80
#define NATTR 85
#define MAXT 64
#define CELLS (NA * NH * NW)   // 17328
#define HW (NH * NW)           // 5776
#define TPB 256
#define ILP 2
#define CPB (ILP * TPB)                    // 512 cells per block
#define BLKX ((CELLS + CPB - 1) / CPB)     // 34
#define AR_LO 0.69f                        // conservative margin around 0.7
#define AR_HI (1.0f / 0.69f)
#define LUTN 64

__device__ double   g_acc;
__device__ unsigned g_cnt;

__constant__ float c_anch[18] = {10.f,13.f, 16.f,30.f, 33.f,23.f, 30.f,61.f, 62.f,45.f,
                                 59.f,119.f, 116.f,90.f, 156.f,198.f, 373.f,326.f};

__device__ __forceinline__ float read_dim(const void* p) {
    if (p == nullptr) return 608.0f;
    int iv = *(const int*)p;
    if (iv > 0 && iv < 1000000) return (float)iv;
    float fv = *(const float*)p;
    if (fv >= 1.0f && fv < 1.0e6f) return fv;
    return 608.0f;
}

__device__ __forceinline__ int expo_idx(float v) {
    int e = (__float_as_int(v) >> 23) & 0xFF;
    return min(max(e - 96, 0), LUTN - 1);
}

__global__ void __launch_bounds__(TPB, 4)
yolo_fused(const float* __restrict__ x, const float* __restrict__ target,
           const void* dimp, int nT, float* __restrict__ out, int nBlocksTotal)
{
    __shared__ float4 s_sbox[MAXT];                // sorted by areaB: bx1,by1,bx2,by2
    __shared__ float  s_sa[MAXT];                  // sorted areaB
    __shared__ float  s_areaB[MAXT];               // unsorted (for ranking + LUT)
    __shared__ float  s_tx[MAXT], s_ty[MAXT], s_tw[MAXT], s_th[MAXT], s_m2[MAXT];
    __shared__ int    s_cls[MAXT];
    __shared__ short  s_lut[LUTN];                 // start index per area-exponent bucket
    __shared__ unsigned s_mask[2];
    __shared__ int    s_win[CPB];
    __shared__ int    s_wlist[MAXT];               // packed (local_cell<<6)|win
    __shared__ int    s_nwin;
    __shared__ double ws[TPB / 32];

    const int b   = blockIdx.y;
    const int tid = threadIdx.x;
    const int lane = tid & 31;
    const int wid  = tid >> 5;
    const int blockStart = blockIdx.x * CPB;
    const float img  = read_dim(dimp);
    const float invs = (float)NH / img;            // 1/stride

    // ---- 1) issue the per-cell GMEM loads FIRST (overlap DRAM latency) ----
    float x0v[ILP], x1v[ILP], px2[ILP], px3[ILP], px4[ILP];
    int ia[ILP], ix[ILP], iy[ILP];
    bool ok[ILP];
    #pragma unroll
    for (int k = 0; k < ILP; k++) {
        const int cell = blockStart + k * TPB + tid;
        ok[k] = (cell < CELLS);
        const int ccl = ok[k] ? cell : (CELLS - 1);
        const int a   = ccl / HW;
        const int rem = ccl - a * HW;
        const int j = rem / NW, i = rem - j * NW;
        ia[k] = a; ix[k] = i; iy[k] = j;
        const float* xb = x + ((size_t)b * (NA * NATTR) + (size_t)a * NATTR) * HW + rem;
        x0v[k] = xb[0];
        x1v[k] = xb[(size_t)HW];
        px2[k] = xb[2 * (size_t)HW];
        px3[k] = xb[3 * (size_t)HW];
        px4[k] = xb[4 * (size_t)HW];
    }

    #pragma unroll
    for (int k = 0; k < ILP; k++) s_win[tid + k * TPB] = -1;
    if (tid == 0) s_nwin = 0;

    // ---- 2) GT validity ballot (warps 0-1) ----
    float t0 = 0.f, t1 = 0.f, t2 = 0.f, t3 = 0.f, t4 = 0.f;
    if (tid < 64) {
        bool nz = false;
        if (tid < nT) {
            const float* tg = target + ((size_t)b * nT + tid) * 5;
            t0 = tg[0]; t1 = tg[1]; t2 = tg[2]; t3 = tg[3]; t4 = tg[4];
            nz = ((t0 + t1 + t2 + t3 + t4) != 0.0f);
        }
        unsigned m = __ballot_sync(0xffffffffu, nz);
        if ((tid & 31) == 0) s_mask[tid >> 5] = m;
    }
    __syncthreads();

    int V;
    {
        unsigned long long mm = (unsigned long long)s_mask[0] |
                                ((unsigned long long)s_mask[1] << 32);
        unsigned long long inv = ~mm;
        V = (inv == 0ull) ? 64 : (__ffsll((long long)inv) - 1);
        V = min(V, nT);
    }

    // ---- 3) GT precompute, area table ----
    float gx = 0.f, gy = 0.f, gw = 0.f, gh = 0.f, myA = 0.f;
    if (tid < V) {
        gx = t1 * NW; gy = t2 * NH; gw = t3 * NW; gh = t4 * NH;
        myA = gw * gh;
        s_areaB[tid] = myA;
        const int gi = min(max((int)gx, 0), NW - 1);
        const int gj = min(max((int)gy, 0), NH - 1);

        int best = 0; float bestr = -1.0f;
        #pragma unroll
        for (int k = 0; k < 9; k++) {
            float aw = c_anch[2*k] * invs, ah = c_anch[2*k+1] * invs;
            float inter = fminf(gw, aw) * fminf(gh, ah);
            float uni   = gw * gh + aw * ah - inter;
            float r = __fdividef(inter, uni + 1e-16f);
            if (r > bestr) { bestr = r; best = k; }
        }
        int aloc = (best < NA) ? best : -1;        // mask = [0,1,2]

        s_tx[tid] = gx - (float)gi;
        s_ty[tid] = gy - (float)gj;
        int al = max(aloc, 0);
        s_tw[tid] = __logf(__fdividef(gw, c_anch[2*al]   * invs) + 1e-16f);
        s_th[tid] = __logf(__fdividef(gh, c_anch[2*al+1] * invs) + 1e-16f);
        s_m2[tid] = 2.0f - t3 * t4;                // coord^2
        s_cls[tid] = min(max((int)t0, 0), NCLS - 1);

        if (aloc >= 0) {
            int cellid = aloc * HW + gj * NW + gi;
            int idx = cellid - blockStart;
            if (idx >= 0 && idx < CPB)
                atomicMax(&s_win[idx], tid);       // max-t == last-t-wins scatter
        }
    }
    __syncthreads();                               // s_areaB ready

    // ---- 4) rank-sort GT boxes by areaB; build exponent-bucket start LUT ----
    if (tid < V) {
        int rank = 0;
        for (int q = 0; q < V; q++) {
            float qa = s_areaB[q];
            rank += (qa < myA) || (qa == myA && q < tid);
        }
        s_sbox[rank] = make_float4(gx - 0.5f * gw, gy - 0.5f * gh,
                                   gx + 0.5f * gw, gy + 0.5f * gh);
        s_sa[rank] = myA;
    } else if (tid >= 64 && tid < 64 + LUTN) {     // separate warps build the LUT
        const int e = tid - 64;
        int cnt = 0;
        for (int q = 0; q < V; q++)
            cnt += (expo_idx(s_areaB[q]) < e);
        s_lut[e] = (short)cnt;                     // first sorted idx with bucket >= e
    }

    // ---- 5) per-cell geometry (loads arrived) ----
    float ax1[ILP], ax2[ILP], ay1[ILP], ay2[ILP], base[ILP], areaA[ILP];
    float psx[ILP], psy[ILP];
    #pragma unroll
    for (int k = 0; k < ILP; k++) {
        const float aw = c_anch[2*ia[k]] * invs, ah = c_anch[2*ia[k]+1] * invs;
        psx[k] = __fdividef(1.0f, 1.0f + __expf(-x0v[k]));
        psy[k] = __fdividef(1.0f, 1.0f + __expf(-x1v[k]));
        const float pw = __expf(px2[k]) * aw, ph = __expf(px3[k]) * ah;
        const float cx = psx[k] + (float)ix[k], cy = psy[k] + (float)iy[k];
        ax1[k] = cx - 0.5f * pw; ax2[k] = cx + 0.5f * pw;
        ay1[k] = cy - 0.5f * ph; ay2[k] = cy + 0.5f * ph;
        areaA[k] = pw * ph;
        base[k] = (7.0f / 17.0f) * (areaA[k] + 1e-16f);
    }

    __syncthreads();                               // sorted tables + LUT + scatter ready

    // ---- 6) pruned ignore test + fused epilogue ----
    float loss = 0.0f;
    #pragma unroll
    for (int k = 0; k < ILP; k++) {
        if (!ok[k]) continue;
        const float loKey = AR_LO * areaA[k];
        const float hiKey = AR_HI * areaA[k];
        int t = s_lut[expo_idx(loKey)];            // LUT start (may include a few extras)

        bool ignore = false;
        for (; t < V; t++) {
            const float aB = s_sa[t];
            if (aB >= hiKey) break;                // sorted => done
            const float4 bb = s_sbox[t];
            float iw = fmaxf(fminf(ax2[k], bb.z) - fmaxf(ax1[k], bb.x), 0.0f);
            float ih = fminf(ay2[k], bb.w) - fmaxf(ay1[k], bb.y);
            if (fmaf(iw, ih, -(7.0f / 17.0f) * aB) > base[k]) { ignore = true; break; }
        }

        const int win = s_win[tid + k * TPB];
        if (win >= 0 || !ignore) {
            const float softp = __logf(1.0f + __expf(px4[k]));   // -log(1-sig)+...
            if (!ignore) loss += softp;                          // noobj BCE
            if (win >= 0) {
                loss += softp - px4[k];                          // -log(sig(x4)+eps)
                const float dx = psx[k] - s_tx[win], dy = psy[k] - s_ty[win];
                const float dw = px2[k] - s_tw[win], dh = px3[k] - s_th[win];
                loss += 0.5f * s_m2[win] * (dx*dx + dy*dy + dw*dw + dh*dh);
                const int slot = atomicAdd(&s_nwin, 1);
                s_wlist[slot] = ((k * TPB + tid) << 6) | win;
            }
        }
    }

    __syncthreads();                               // winner list complete

    // ---- 7) cooperative class BCE: warp e%8 drains entry e (32 lanes x 3 cls) ----
    const int nw = s_nwin;
    for (int e = wid; e < nw; e += TPB / 32) {
        const int packed = s_wlist[e];
        const int lcl = packed >> 6;
        const int wsrc = packed & 63;
        const int cell = blockStart + lcl;
        const int a   = cell / HW;
        const int rem = cell - a * HW;
        const float* xb = x + ((size_t)b * (NA * NATTR) + (size_t)a * NATTR) * HW + rem;
        const int ccls = s_cls[wsrc];
        float part = 0.0f;
        #pragma unroll
        for (int q = 0; q < 3; q++) {
            const int c = lane + q * 32;
            if (c < NCLS) {
                const float v = xb[(size_t)(5 + c) * HW];
                float lc = __logf(1.0f + __expf(v));   // -log(1-sig(v)+eps)
                part += (c == ccls) ? (lc - v) : lc;   // -log(sig(v)+eps)
            }
        }
        loss += part;
    }

    // ---- 8) reduction: warp f32 -> block f64 -> global f64 atomic ----
    #pragma unroll
    for (int o = 16; o > 0; o >>= 1) loss += __shfl_down_sync(0xffffffffu, loss, o);
    if (lane == 0) ws[wid] = (double)loss;
    __syncthreads();
    if (wid == 0) {
        double v = (lane < TPB / 32) ? ws[lane] : 0.0;
        #pragma unroll
        for (int o = 4; o > 0; o >>= 1) v += __shfl_down_sync(0xffffffffu, v, o);
        if (lane == 0) {
            atomicAdd(&g_acc, v);
            __threadfence();
            unsigned done = atomicInc(&g_cnt, 0xffffffffu);
            if (done == (unsigned)(nBlocksTotal - 1)) {
                __threadfence();
                out[0] = (float)(*((volatile double*)&g_acc));
                g_acc = 0.0;                       // reset for next graph replay
                g_cnt = 0u;
            }
        }
    }
}

extern "C" void kernel_launch(void* const* d_in, const int* in_sizes, int n_in,
                              void* d_out, int out_size) {
    const float* x      = (const float*)d_in[0];
    const float* target = (const float*)d_in[1];
    const void*  dimp   = (n_in > 2) ? d_in[2] : nullptr;

    int nB = in_sizes[0] / (NA * NATTR * NH * NW);
    if (nB < 1) nB = 1;
    int nT = in_sizes[1] / (nB * 5);
    if (nT > MAXT) nT = MAXT;
    if (nT < 1) nT = 1;

    dim3 grid(BLKX, nB);
    yolo_fused<<<grid, TPB>>>(x, target, dimp, nT, (float*)d_out,
                              (int)(BLKX * nB));
}

// round 15
// speedup vs baseline: 1.1419x; 1.1419x over previous
#include <cuda_runtime.h>
#include <math.h>

#define NH 76
#define NW 76
#define NA 3
#define NCLS 80
#define NATTR 85
#define MAXT 64
#define CELLS (NA * NH * NW)   // 17328
#define HW (NH * NW)           // 5776
#define TPB 192
#define NWARP (TPB / 32)                   // 6
#define ILP 2
#define CPB (ILP * TPB)                    // 384 cells per block
#define BLKX ((CELLS + CPB - 1) / CPB)     // 46  -> 46*16=736 blocks ~= 148*5 capacity
#define AR_LO 0.69f                        // conservative margin around 0.7
#define AR_HI (1.0f / 0.69f)

__device__ double   g_acc;
__device__ unsigned g_cnt;

__constant__ float c_anch[18] = {10.f,13.f, 16.f,30.f, 33.f,23.f, 30.f,61.f, 62.f,45.f,
                                 59.f,119.f, 116.f,90.f, 156.f,198.f, 373.f,326.f};

__device__ __forceinline__ float read_dim(const void* p) {
    if (p == nullptr) return 608.0f;
    int iv = *(const int*)p;
    if (iv > 0 && iv < 1000000) return (float)iv;
    float fv = *(const float*)p;
    if (fv >= 1.0f && fv < 1.0e6f) return fv;
    return 608.0f;
}

__global__ void __launch_bounds__(TPB, 5)
yolo_fused(const float* __restrict__ x, const float* __restrict__ target,
           const void* dimp, int nT, float* __restrict__ out, int nBlocksTotal)
{
    __shared__ float4 s_sbox[MAXT];                // sorted by areaB: bx1,by1,bx2,by2
    __shared__ float  s_sa[MAXT];                  // sorted areaB
    __shared__ float  s_areaB[MAXT];               // unsorted (for ranking)
    __shared__ float  s_tx[MAXT], s_ty[MAXT], s_tw[MAXT], s_th[MAXT], s_m2[MAXT];
    __shared__ int    s_cls[MAXT];
    __shared__ unsigned s_mask[2];
    __shared__ int    s_win[CPB];
    __shared__ int    s_wlist[MAXT];               // packed (local_cell<<6)|win
    __shared__ int    s_nwin;
    __shared__ double ws[NWARP];

    const int b   = blockIdx.y;
    const int tid = threadIdx.x;
    const int lane = tid & 31;
    const int wid  = tid >> 5;
    const int blockStart = blockIdx.x * CPB;
    const float img  = read_dim(dimp);
    const float invs = (float)NH / img;            // 1/stride

    // ---- 1) issue the per-cell GMEM loads FIRST (overlap DRAM latency) ----
    float x0v[ILP], x1v[ILP], px2[ILP], px3[ILP], px4[ILP];
    int ia[ILP], ix[ILP], iy[ILP];
    bool ok[ILP];
    #pragma unroll
    for (int k = 0; k < ILP; k++) {
        const int cell = blockStart + k * TPB + tid;
        ok[k] = (cell < CELLS);
        const int ccl = ok[k] ? cell : (CELLS - 1);
        const int a   = ccl / HW;
        const int rem = ccl - a * HW;
        const int j = rem / NW, i = rem - j * NW;
        ia[k] = a; ix[k] = i; iy[k] = j;
        const float* xb = x + ((size_t)b * (NA * NATTR) + (size_t)a * NATTR) * HW + rem;
        x0v[k] = xb[0];
        x1v[k] = xb[(size_t)HW];
        px2[k] = xb[2 * (size_t)HW];
        px3[k] = xb[3 * (size_t)HW];
        px4[k] = xb[4 * (size_t)HW];
    }

    #pragma unroll
    for (int k = 0; k < ILP; k++) s_win[tid + k * TPB] = -1;
    if (tid == 0) s_nwin = 0;

    // ---- 2) GT validity ballot (warps 0-1) ----
    float t0 = 0.f, t1 = 0.f, t2 = 0.f, t3 = 0.f, t4 = 0.f;
    if (tid < 64) {
        bool nz = false;
        if (tid < nT) {
            const float* tg = target + ((size_t)b * nT + tid) * 5;
            t0 = tg[0]; t1 = tg[1]; t2 = tg[2]; t3 = tg[3]; t4 = tg[4];
            nz = ((t0 + t1 + t2 + t3 + t4) != 0.0f);
        }
        unsigned m = __ballot_sync(0xffffffffu, nz);
        if ((tid & 31) == 0) s_mask[tid >> 5] = m;
    }
    __syncthreads();

    int V;
    {
        unsigned long long mm = (unsigned long long)s_mask[0] |
                                ((unsigned long long)s_mask[1] << 32);
        unsigned long long inv = ~mm;
        V = (inv == 0ull) ? 64 : (__ffsll((long long)inv) - 1);
        V = min(V, nT);
    }

    // ---- 3) GT precompute, area table ----
    float gx = 0.f, gy = 0.f, gw = 0.f, gh = 0.f, myA = 0.f;
    if (tid < V) {
        gx = t1 * NW; gy = t2 * NH; gw = t3 * NW; gh = t4 * NH;
        myA = gw * gh;
        s_areaB[tid] = myA;
        const int gi = min(max((int)gx, 0), NW - 1);
        const int gj = min(max((int)gy, 0), NH - 1);

        int best = 0; float bestr = -1.0f;
        #pragma unroll
        for (int k = 0; k < 9; k++) {
            float aw = c_anch[2*k] * invs, ah = c_anch[2*k+1] * invs;
            float inter = fminf(gw, aw) * fminf(gh, ah);
            float uni   = gw * gh + aw * ah - inter;
            float r = __fdividef(inter, uni + 1e-16f);
            if (r > bestr) { bestr = r; best = k; }
        }
        int aloc = (best < NA) ? best : -1;        // mask = [0,1,2]

        s_tx[tid] = gx - (float)gi;
        s_ty[tid] = gy - (float)gj;
        int al = max(aloc, 0);
        s_tw[tid] = __logf(__fdividef(gw, c_anch[2*al]   * invs) + 1e-16f);
        s_th[tid] = __logf(__fdividef(gh, c_anch[2*al+1] * invs) + 1e-16f);
        s_m2[tid] = 2.0f - t3 * t4;                // coord^2
        s_cls[tid] = min(max((int)t0, 0), NCLS - 1);

        if (aloc >= 0) {
            int cellid = aloc * HW + gj * NW + gi;
            int idx = cellid - blockStart;
            if (idx >= 0 && idx < CPB)
                atomicMax(&s_win[idx], tid);       // max-t == last-t-wins scatter
        }
    }
    __syncthreads();                               // s_areaB ready

    // ---- 4) rank-sort GT boxes by areaB (V<=64, O(V) per thread) ----
    if (tid < V) {
        int rank = 0;
        for (int q = 0; q < V; q++) {
            float qa = s_areaB[q];
            rank += (qa < myA) || (qa == myA && q < tid);
        }
        s_sbox[rank] = make_float4(gx - 0.5f * gw, gy - 0.5f * gh,
                                   gx + 0.5f * gw, gy + 0.5f * gh);
        s_sa[rank] = myA;
    }

    // ---- 5) per-cell geometry (loads arrived) ----
    float ax1[ILP], ax2[ILP], ay1[ILP], ay2[ILP], base[ILP], areaA[ILP];
    float psx[ILP], psy[ILP], softp[ILP];
    #pragma unroll
    for (int k = 0; k < ILP; k++) {
        const float aw = c_anch[2*ia[k]] * invs, ah = c_anch[2*ia[k]+1] * invs;
        psx[k] = __fdividef(1.0f, 1.0f + __expf(-x0v[k]));
        psy[k] = __fdividef(1.0f, 1.0f + __expf(-x1v[k]));
        const float pw = __expf(px2[k]) * aw, ph = __expf(px3[k]) * ah;
        const float cx = psx[k] + (float)ix[k], cy = psy[k] + (float)iy[k];
        ax1[k] = cx - 0.5f * pw; ax2[k] = cx + 0.5f * pw;
        ay1[k] = cy - 0.5f * ph; ay2[k] = cy + 0.5f * ph;
        areaA[k] = pw * ph;
        base[k] = (7.0f / 17.0f) * (areaA[k] + 1e-16f);
        softp[k] = __logf(1.0f + __expf(px4[k]));  // -log(1-sig(x4)+eps)
    }

    __syncthreads();                               // sorted tables + scatter ready

    // ---- 6) winner scalar terms by owner; enqueue class-BCE work ----
    float loss = 0.0f;
    #pragma unroll
    for (int k = 0; k < ILP; k++) {
        const int win = s_win[tid + k * TPB];
        if (win >= 0 && ok[k]) {
            loss += softp[k] - px4[k];             // -log(sig(x4)+eps)
            const float dx = psx[k] - s_tx[win], dy = psy[k] - s_ty[win];
            const float dw = px2[k] - s_tw[win], dh = px3[k] - s_th[win];
            loss += 0.5f * s_m2[win] * (dx*dx + dy*dy + dw*dw + dh*dh);
            const int slot = atomicAdd(&s_nwin, 1);
            s_wlist[slot] = ((k * TPB + tid) << 6) | win;
        }
    }

    // ---- 7) pruned ignore test: only GTs with areaB in (0.69*areaA, areaA/0.69) ----
    #pragma unroll
    for (int k = 0; k < ILP; k++) {
        if (!ok[k]) continue;
        const float loKey = AR_LO * areaA[k];
        const float hiKey = AR_HI * areaA[k];

        int lo = 0, hi = V;                        // first idx with s_sa[idx] > loKey
        while (lo < hi) {
            int m = (lo + hi) >> 1;
            if (s_sa[m] <= loKey) lo = m + 1; else hi = m;
        }

        bool ignore = false;
        for (int t = lo; t < V; t++) {
            const float aB = s_sa[t];
            if (aB >= hiKey) break;                // sorted => done
            const float4 bb = s_sbox[t];
            float iw = fmaxf(fminf(ax2[k], bb.z) - fmaxf(ax1[k], bb.x), 0.0f);
            float ih = fminf(ay2[k], bb.w) - fmaxf(ay1[k], bb.y);
            if (fmaf(iw, ih, -(7.0f / 17.0f) * aB) > base[k]) { ignore = true; break; }
        }
        if (!ignore) loss += softp[k];             // noobj BCE
    }

    __syncthreads();                               // winner list complete

    // ---- 8) cooperative class BCE: warp e%NWARP drains entry e (32 lanes x 3 cls) ----
    const int nw = s_nwin;
    for (int e = wid; e < nw; e += NWARP) {
        const int packed = s_wlist[e];
        const int lcl = packed >> 6;
        const int wsrc = packed & 63;
        const int cell = blockStart + lcl;
        const int a   = cell / HW;
        const int rem = cell - a * HW;
        const float* xb = x + ((size_t)b * (NA * NATTR) + (size_t)a * NATTR) * HW + rem;
        const int ccls = s_cls[wsrc];
        float part = 0.0f;
        #pragma unroll
        for (int q = 0; q < 3; q++) {
            const int c = lane + q * 32;
            if (c < NCLS) {
                const float v = xb[(size_t)(5 + c) * HW];
                float lc = __logf(1.0f + __expf(v));   // -log(1-sig(v)+eps)
                part += (c == ccls) ? (lc - v) : lc;   // -log(sig(v)+eps)
            }
        }
        loss += part;
    }

    // ---- 9) reduction: warp f32 -> block f64 -> global f64 atomic ----
    #pragma unroll
    for (int o = 16; o > 0; o >>= 1) loss += __shfl_down_sync(0xffffffffu, loss, o);
    if (lane == 0) ws[wid] = (double)loss;
    __syncthreads();
    if (wid == 0) {
        double v = (lane < NWARP) ? ws[lane] : 0.0;
        #pragma unroll
        for (int o = 4; o > 0; o >>= 1) v += __shfl_down_sync(0xffffffffu, v, o);
        if (lane == 0) {
            atomicAdd(&g_acc, v);
            __threadfence();
            unsigned done = atomicInc(&g_cnt, 0xffffffffu);
            if (done == (unsigned)(nBlocksTotal - 1)) {
                __threadfence();
                out[0] = (float)(*((volatile double*)&g_acc));
                g_acc = 0.0;                       // reset for next graph replay
                g_cnt = 0u;
            }
        }
    }
}

extern "C" void kernel_launch(void* const* d_in, const int* in_sizes, int n_in,
                              void* d_out, int out_size) {
    const float* x      = (const float*)d_in[0];
    const float* target = (const float*)d_in[1];
    const void*  dimp   = (n_in > 2) ? d_in[2] : nullptr;

    int nB = in_sizes[0] / (NA * NATTR * NH * NW);
    if (nB < 1) nB = 1;
    int nT = in_sizes[1] / (nB * 5);
    if (nT > MAXT) nT = MAXT;
    if (nT < 1) nT = 1;

    dim3 grid(BLKX, nB);
    yolo_fused<<<grid, TPB>>>(x, target, dimp, nT, (float*)d_out,
                              (int)(BLKX * nB));
}